// round 9
// baseline (speedup 1.0000x reference)
#include <cuda_runtime.h>

#define Bn   1024
#define Kseg 160
#define WS   12
#define G    36
#define DH   1024
#define TPAD 164            // Kseg + 4 prefetch pad
#define STR4 (Bn * WS)      // float4 stride between t slots in g_gi

#define SCL1 1.442695040888963f   // log2(e)
#define SCL2 2.885390081777927f   // 2*log2(e)

// Scratch (static device globals — no allocation)
__device__ float4 g_gi[TPAD * Bn * WS];        // [t][b][j] prescaled {r,z,n,0}
__device__ float4 g_pegi4[TPAD * WS];          // [t][j] prescaled {pr,pz,pn,0}
__device__ float4 g_wdec[(Kseg + 4) * WS * 4]; // [k][j][4]: w0..3,w4..7,w8..11,{beff,..}

__device__ __forceinline__ float fex2(float x) {
    float y; asm("ex2.approx.f32 %0, %1;" : "=f"(y) : "f"(x)); return y;
}
__device__ __forceinline__ float frcp(float x) {
    float y; asm("rcp.approx.f32 %0, %1;" : "=f"(y) : "f"(x)); return y;
}

// ---------------------------------------------------------------------------
// Prep kernel: blocks 0..639 = encoder+gi, 640..799 = weff fold, 800 = pegi.
// One launch so the independent pieces overlap across SMs.
// ---------------------------------------------------------------------------
__global__ void __launch_bounds__(256) prep_kernel(
        const float* __restrict__ x,
        const float* __restrict__ enc_W,
        const float* __restrict__ enc_b,
        const float* __restrict__ Wih,
        const float* __restrict__ bih,
        const float* __restrict__ bhh,
        const float* __restrict__ dec_W1,
        const float* __restrict__ dec_b1,
        const float* __restrict__ dec_W2,
        const float* __restrict__ dec_b2) {
    __shared__ float sraw[DH * WS];   // 48 KB, reused by both branches

    if (blockIdx.x < 640) {
        // ------------------- encoder + gi -------------------
        float* sWih = sraw;            // 432
        float* sEW  = sraw + 432;      // 144
        float* sEB  = sraw + 576;      // 12
        float* sBI  = sraw + 588;      // 36
        float* sg   = sraw + 640;      // 256*37 = 9472
        int k = blockIdx.x >> 2;
        int bbase = (blockIdx.x & 3) << 8;
        int b = bbase + threadIdx.x;

        for (int t = threadIdx.x; t < G * WS; t += 256) sWih[t] = Wih[t];
        {
            int t = threadIdx.x;
            if (t < WS * WS) sEW[t] = enc_W[k * (WS * WS) + t];
            if (t < WS) sEB[t] = enc_b[k * WS + t];
            if (t < G) sBI[t] = bih[t] + ((t < 24) ? bhh[t] : 0.0f);
        }
        __syncthreads();

        const float4* xr4 = (const float4*)(x + (size_t)b * 1920 + k * WS);
        float4 x0 = xr4[0], x1 = xr4[1], x2 = xr4[2];
        float xv[WS] = {x0.x, x0.y, x0.z, x0.w, x1.x, x1.y, x1.z, x1.w,
                        x2.x, x2.y, x2.z, x2.w};

        float xs[WS];
#pragma unroll
        for (int o = 0; o < WS; ++o) {
            float a = sEB[o];
#pragma unroll
            for (int i = 0; i < WS; ++i) a = fmaf(xv[i], sEW[i * WS + o], a);
            xs[o] = fmaxf(a, 0.0f);
        }

        float* sgr = sg + threadIdx.x * 37;
#pragma unroll
        for (int g = 0; g < G; ++g) {
            float a = sBI[g];
#pragma unroll
            for (int o = 0; o < WS; ++o) a = fmaf(xs[o], sWih[g * WS + o], a);
            sgr[g] = a;
        }
        __syncthreads();

        float4* dst = g_gi + ((size_t)k * Bn + bbase) * WS;
        for (int i = threadIdx.x; i < 256 * WS; i += 256) {
            int bl = i / WS;
            int j = i - bl * WS;
            const float* s = sg + bl * 37 + j;
            dst[i] = make_float4(-SCL1 * s[0], -SCL1 * s[12], -SCL2 * s[24], 0.0f);
        }
        return;
    }

    if (blockIdx.x == 800) {
        // ------------------- pegi table -------------------
        int k = threadIdx.x;
        if (k >= Kseg) return;
        float pe[WS];
        const float c = -9.210340371976184f / 12.0f;   // -ln(10000)/d
#pragma unroll
        for (int j = 0; j < 6; ++j) {
            float div = expf(c * (float)(2 * j));
            float ang = (float)k * div;
            pe[2 * j]     = sinf(ang);
            pe[2 * j + 1] = cosf(ang);
        }
        float ch = sinf((float)k);
#pragma unroll
        for (int o = 0; o < WS; ++o) pe[o] += ch;
        float pg[G];
#pragma unroll
        for (int g = 0; g < G; ++g) {
            float a = 0.0f;
#pragma unroll
            for (int o = 0; o < WS; ++o) a = fmaf(pe[o], Wih[g * WS + o], a);
            pg[g] = a;
        }
#pragma unroll
        for (int j = 0; j < WS; ++j)
            g_pegi4[k * WS + j] = make_float4(-SCL1 * pg[j], -SCL1 * pg[12 + j],
                                              -SCL2 * pg[24 + j], 0.0f);
        return;
    }

    // ------------------- weff fold (k = blockIdx-640) -------------------
    {
        float* w2s = sraw;
        int k = blockIdx.x - 640;
        const float4* W24 = (const float4*)(dec_W2 + (size_t)k * DH * WS);
        float4* w2s4 = (float4*)w2s;
        for (int i = threadIdx.x; i < DH * WS / 4; i += 256) w2s4[i] = W24[i];
        __syncthreads();

        float* wdecF = (float*)g_wdec;        // [k][j][16] floats
        int t = threadIdx.x;
        if (t < 144) {
            int d = t / WS, o = t - (t / WS) * WS;
            const float4* w14 = (const float4*)(dec_W1 + ((size_t)k * WS + d) * DH);
            float a0 = 0.f, a1 = 0.f, a2 = 0.f, a3 = 0.f;
            float a4 = 0.f, a5 = 0.f, a6 = 0.f, a7 = 0.f;
            for (int q = 0; q < DH / 4; q += 2) {
                float4 u = w14[q], v = w14[q + 1];
                int h = q * 4;
                a0 = fmaf(u.x, w2s[(h + 0) * WS + o], a0);
                a1 = fmaf(u.y, w2s[(h + 1) * WS + o], a1);
                a2 = fmaf(u.z, w2s[(h + 2) * WS + o], a2);
                a3 = fmaf(u.w, w2s[(h + 3) * WS + o], a3);
                a4 = fmaf(v.x, w2s[(h + 4) * WS + o], a4);
                a5 = fmaf(v.y, w2s[(h + 5) * WS + o], a5);
                a6 = fmaf(v.z, w2s[(h + 6) * WS + o], a6);
                a7 = fmaf(v.w, w2s[(h + 7) * WS + o], a7);
            }
            wdecF[((size_t)k * WS + o) * 16 + d] =
                ((a0 + a1) + (a2 + a3)) + ((a4 + a5) + (a6 + a7));
        } else if (t < 156) {
            int o = t - 144;
            const float4* b14 = (const float4*)(dec_b1 + (size_t)k * DH);
            float a0 = dec_b2[k * WS + o], a1 = 0.f, a2 = 0.f, a3 = 0.f;
            for (int q = 0; q < DH / 4; ++q) {
                float4 u = b14[q];
                int h = q * 4;
                a0 = fmaf(u.x, w2s[(h + 0) * WS + o], a0);
                a1 = fmaf(u.y, w2s[(h + 1) * WS + o], a1);
                a2 = fmaf(u.z, w2s[(h + 2) * WS + o], a2);
                a3 = fmaf(u.w, w2s[(h + 3) * WS + o], a3);
            }
            wdecF[((size_t)k * WS + o) * 16 + 12] = (a0 + a1) + (a2 + a3);
        }
    }
}

// ---------------------------------------------------------------------------
// RNN kernel: ONE WARP PER ROW (1024 warps). Lanes 0-11 compute the r-gate
// dot, lanes 16-27 compute the z-gate dot in the SAME instructions. The
// n-dot (low half) shares its FMA slots with the fused decoder dot (high
// half) in phase 2; decoder weights are refreshed by predicated LDG.128
// (off-lanes keep the persistent n-weights).
// ---------------------------------------------------------------------------
__global__ void __launch_bounds__(32) rnn_kernel(const float* __restrict__ Whh,
                                                 const float* __restrict__ bhh,
                                                 float* __restrict__ out) {
    const unsigned FULL = 0xffffffffu;
    int lane = threadIdx.x;
    int half = lane >> 4;            // 0 = r/n side, 1 = z/dec side
    int l = lane & 15;
    int j = (l < WS) ? l : (WS - 1);
    int row = blockIdx.x;
    bool hstore = (half == 1) && (l < WS);   // dec output lanes

    // wA: low = -S1*Whh_r[j], high = -S1*Whh_z[j]
    float wA[12];
    {
        const float* wrow = Whh + (half ? (12 + j) : j) * 12;
#pragma unroll
        for (int i = 0; i < 12; ++i) wA[i] = -SCL1 * wrow[i];
    }

    // n-weight / decoder double buffers (float4 x4 each).
    float4 nA0, nA1, nA2, nA3, nB0, nB1, nB2, nB3;
    if (half == 0) {
        const float* wn = Whh + (24 + j) * 12;
        nA0 = make_float4(-SCL2 * wn[0], -SCL2 * wn[1], -SCL2 * wn[2], -SCL2 * wn[3]);
        nA1 = make_float4(-SCL2 * wn[4], -SCL2 * wn[5], -SCL2 * wn[6], -SCL2 * wn[7]);
        nA2 = make_float4(-SCL2 * wn[8], -SCL2 * wn[9], -SCL2 * wn[10], -SCL2 * wn[11]);
        nA3 = make_float4(-SCL2 * bhh[24 + j], 0.f, 0.f, 0.f);
        nB0 = nA0; nB1 = nA1; nB2 = nA2; nB3 = nA3;
    } else {
        nA0 = nA1 = nA2 = nA3 = make_float4(0.f, 0.f, 0.f, 0.f);
        nB0 = nB1 = nB2 = nB3 = nA0;
    }

    const float4* pA = g_gi + (size_t)row * WS + j;
    const float4* pegp = g_pegi4 + j;
    const float4* wdp = g_wdec + (size_t)j * 4;      // + k*48
    float* outp = out + (size_t)row * 1920 + j;

    float h = 0.0f;
    float hx[12];
    float4 a0, a1, a2, a3;
    const float4* q;

#define HBCAST()                                                        \
    {                                                                   \
        _Pragma("unroll")                                               \
        for (int i = 0; i < 12; ++i) hx[i] = __shfl_sync(FULL, h, i);   \
    }

    // one GRU step; gv = gi float4 (+pegi already added for phase 2 via args)
#define GSTEP(GA, GN, N0, N1, N2, N3)                                   \
    {                                                                   \
        float ac0 = (GA), ac1 = 0.f;                                    \
        _Pragma("unroll")                                               \
        for (int i = 0; i < 12; i += 2) {                               \
            ac0 = fmaf(wA[i], hx[i], ac0);                              \
            ac1 = fmaf(wA[i + 1], hx[i + 1], ac1);                      \
        }                                                               \
        float sgv = frcp(1.0f + fex2(ac0 + ac1));   /* r | z */         \
        float c0 = N3.x, c1 = 0.f, c2 = 0.f, c3 = 0.f;                  \
        c0 = fmaf(N0.x, hx[0], c0); c1 = fmaf(N0.y, hx[1], c1);         \
        c2 = fmaf(N0.z, hx[2], c2); c3 = fmaf(N0.w, hx[3], c3);         \
        c0 = fmaf(N1.x, hx[4], c0); c1 = fmaf(N1.y, hx[5], c1);         \
        c2 = fmaf(N1.z, hx[6], c2); c3 = fmaf(N1.w, hx[7], c3);         \
        c0 = fmaf(N2.x, hx[8], c0); c1 = fmaf(N2.y, hx[9], c1);         \
        c2 = fmaf(N2.z, hx[10], c2); c3 = fmaf(N2.w, hx[11], c3);       \
        csum = (c0 + c1) + (c2 + c3);               /* n-dot | dec */   \
        float zv = __shfl_sync(FULL, sgv, lane | 16);                   \
        float nv = fmaf(2.0f, frcp(1.0f + fex2(fmaf(sgv, csum, (GN)))), -1.0f); \
        h = fmaf(zv, h - nv, nv);                                       \
    }

    float csum;

    // ---------------- phase 1: first GRU (keep only final h) ---------------
    a0 = pA[0];
    a1 = pA[STR4];
    a2 = pA[2 * STR4];
    a3 = pA[3 * STR4];
    q = pA + 4 * STR4;
    for (int t = 0; t < Kseg; t += 4) {
        float ga, gn;
        HBCAST();
        ga = half ? a0.y : a0.x; gn = a0.z;
        GSTEP(ga, gn, nA0, nA1, nA2, nA3);
        a0 = q[0];
        HBCAST();
        ga = half ? a1.y : a1.x; gn = a1.z;
        GSTEP(ga, gn, nB0, nB1, nB2, nB3);
        a1 = q[STR4];
        HBCAST();
        ga = half ? a2.y : a2.x; gn = a2.z;
        GSTEP(ga, gn, nA0, nA1, nA2, nA3);
        a2 = q[2 * STR4];
        HBCAST();
        ga = half ? a3.y : a3.x; gn = a3.z;
        GSTEP(ga, gn, nB0, nB1, nB2, nB3);
        a3 = q[3 * STR4];
        q += 4 * STR4;
    }

    // ---------------- phase 2: second GRU + fused decoder -------------------
    a0 = pA[0];
    a1 = pA[STR4];
    a2 = pA[2 * STR4];
    a3 = pA[3 * STR4];
    q = pA + 4 * STR4;
    float4 p0 = pegp[0], p1 = pegp[WS], p2 = pegp[2 * WS], p3 = pegp[3 * WS];
    const float4* pq = pegp + 4 * WS;

    // preload bufB <- wdec[0] (high half only; low half keeps n-weights)
    if (half) {
        const float4* wb = wdp;        // k = 0
        nB0 = wb[0]; nB1 = wb[1]; nB2 = wb[2]; nB3 = wb[3];
    }

#define STEP2(AR, PR, NU0, NU1, NU2, NU3, TT)                           \
    {                                                                   \
        HBCAST();                                                       \
        float ga = (half ? AR.y : AR.x) + (half ? PR.y : PR.x);         \
        float gn = AR.z + PR.z;                                         \
        GSTEP(ga, gn, NU0, NU1, NU2, NU3);                              \
        if (hstore && (TT) > 0) outp[((TT) - 1) * 12] = csum;           \
        if (half) {                                                     \
            const float4* wb = wdp + (size_t)((TT) + 1) * 48;           \
            NU0 = wb[0]; NU1 = wb[1]; NU2 = wb[2]; NU3 = wb[3];         \
        }                                                               \
    }

    for (int t = 0; t < Kseg; t += 4) {
        STEP2(a0, p0, nA0, nA1, nA2, nA3, t + 0);
        a0 = q[0];          p0 = pq[0];
        STEP2(a1, p1, nB0, nB1, nB2, nB3, t + 1);
        a1 = q[STR4];       p1 = pq[WS];
        STEP2(a2, p2, nA0, nA1, nA2, nA3, t + 2);
        a2 = q[2 * STR4];   p2 = pq[2 * WS];
        STEP2(a3, p3, nB0, nB1, nB2, nB3, t + 3);
        a3 = q[3 * STR4];   p3 = pq[3 * WS];
        q += 4 * STR4;      pq += 4 * WS;
    }
#undef STEP2

    // tail: out[Kseg-1] uses bufA (holds wdec[159], loaded at t=158)
    {
        HBCAST();
        float c0 = nA3.x, c1 = 0.f, c2 = 0.f, c3 = 0.f;
        c0 = fmaf(nA0.x, hx[0], c0); c1 = fmaf(nA0.y, hx[1], c1);
        c2 = fmaf(nA0.z, hx[2], c2); c3 = fmaf(nA0.w, hx[3], c3);
        c0 = fmaf(nA1.x, hx[4], c0); c1 = fmaf(nA1.y, hx[5], c1);
        c2 = fmaf(nA1.z, hx[6], c2); c3 = fmaf(nA1.w, hx[7], c3);
        c0 = fmaf(nA2.x, hx[8], c0); c1 = fmaf(nA2.y, hx[9], c1);
        c2 = fmaf(nA2.z, hx[10], c2); c3 = fmaf(nA2.w, hx[11], c3);
        float oa = (c0 + c1) + (c2 + c3);
        if (hstore) outp[(Kseg - 1) * 12] = oa;
    }
#undef GSTEP
#undef HBCAST
}

// ---------------------------------------------------------------------------
extern "C" void kernel_launch(void* const* d_in, const int* in_sizes, int n_in,
                              void* d_out, int out_size) {
    const float* x     = (const float*)d_in[0];
    const float* enc_W = (const float*)d_in[1];
    const float* enc_b = (const float*)d_in[2];
    const float* Wih   = (const float*)d_in[3];
    const float* Whh   = (const float*)d_in[4];
    const float* bih   = (const float*)d_in[5];
    const float* bhh   = (const float*)d_in[6];
    const float* dW1   = (const float*)d_in[7];
    const float* db1   = (const float*)d_in[8];
    const float* dW2   = (const float*)d_in[9];
    const float* db2   = (const float*)d_in[10];
    float* out = (float*)d_out;

    prep_kernel<<<801, 256>>>(x, enc_W, enc_b, Wih, bih, bhh,
                              dW1, db1, dW2, db2);
    rnn_kernel<<<1024, 32>>>(Whh, bhh, out);
}

// round 10
// speedup vs baseline: 1.0005x; 1.0005x over previous
#include <cuda_runtime.h>

#define Bn   1024
#define Kseg 160
#define WS   12
#define G    36
#define DH   1024
#define TPAD 164            // Kseg + 4 prefetch pad
#define STR4 (Bn * WS)      // float4 stride between t slots

#define SCL2 2.885390081777927f   // 2*log2(e)

// Scratch (static device globals — no allocation)
__device__ float4 g_gi[TPAD * Bn * WS];    // [t][b][j] = {0.5*r, 0.5*z, -S2*n, 0}
__device__ float4 g_gi2[TPAD * Bn * WS];   // same, with pe-gates folded in (phase 2)
__device__ float4 g_wdec[Kseg * WS * 4];   // [k][j][4]: w0..3,w4..7,w8..11,{beff,..}

__device__ __forceinline__ float fex2(float x) {
    float y; asm("ex2.approx.f32 %0, %1;" : "=f"(y) : "f"(x)); return y;
}
__device__ __forceinline__ float frcp(float x) {
    float y; asm("rcp.approx.f32 %0, %1;" : "=f"(y) : "f"(x)); return y;
}
__device__ __forceinline__ float ftanh(float x) {
    float y; asm("tanh.approx.f32 %0, %1;" : "=f"(y) : "f"(x)); return y;
}

// ---------------------------------------------------------------------------
// Prep kernel: blocks 0..639 = encoder + gi + gi2 (pe-gates computed inline
// per block), blocks 640..799 = weff fold.
// ---------------------------------------------------------------------------
__global__ void __launch_bounds__(256) prep_kernel(
        const float* __restrict__ x,
        const float* __restrict__ enc_W,
        const float* __restrict__ enc_b,
        const float* __restrict__ Wih,
        const float* __restrict__ bih,
        const float* __restrict__ bhh,
        const float* __restrict__ dec_W1,
        const float* __restrict__ dec_b1,
        const float* __restrict__ dec_W2,
        const float* __restrict__ dec_b2) {
    __shared__ float sraw[DH * WS];   // 48 KB, reused by both branches

    if (blockIdx.x < 640) {
        // ------------------- encoder + gi + gi2 -------------------
        float* sWih = sraw;            // [0,432)
        float* sEW  = sraw + 432;      // [432,576)
        float* sEB  = sraw + 576;      // [576,588)
        float* sBI  = sraw + 588;      // [588,624)
        float* spe  = sraw + 624;      // [624,636)  pe vector for this k
        float* spg  = sraw + 640;      // [640,676)  pe-gates for this k
        float* sg   = sraw + 704;      // [704, 704+9472)
        int k = blockIdx.x >> 2;
        int bbase = (blockIdx.x & 3) << 8;
        int b = bbase + threadIdx.x;

        for (int t = threadIdx.x; t < G * WS; t += 256) sWih[t] = Wih[t];
        {
            int t = threadIdx.x;
            if (t < WS * WS) sEW[t] = enc_W[k * (WS * WS) + t];
            if (t < WS) sEB[t] = enc_b[k * WS + t];
            if (t < G) sBI[t] = bih[t] + ((t < 24) ? bhh[t] : 0.0f);
            if (t < 6) {
                const float c = -9.210340371976184f / 12.0f;   // -ln(10000)/d
                float div = expf(c * (float)(2 * t));
                float ang = (float)k * div;
                spe[2 * t]     = sinf(ang);
                spe[2 * t + 1] = cosf(ang);
            }
        }
        __syncthreads();

        // pe-gates (threads 0..35), concurrent with xs/gi compute below
        if (threadIdx.x < G) {
            int g = threadIdx.x;
            float ch = sinf((float)k);
            float a = 0.0f;
#pragma unroll
            for (int o = 0; o < WS; ++o)
                a = fmaf(spe[o] + ch, sWih[g * WS + o], a);
            spg[g] = a;
        }

        const float4* xr4 = (const float4*)(x + (size_t)b * 1920 + k * WS);
        float4 x0 = xr4[0], x1 = xr4[1], x2 = xr4[2];
        float xv[WS] = {x0.x, x0.y, x0.z, x0.w, x1.x, x1.y, x1.z, x1.w,
                        x2.x, x2.y, x2.z, x2.w};

        float xs[WS];
#pragma unroll
        for (int o = 0; o < WS; ++o) {
            float a = sEB[o];
#pragma unroll
            for (int i = 0; i < WS; ++i) a = fmaf(xv[i], sEW[i * WS + o], a);
            xs[o] = fmaxf(a, 0.0f);
        }

        float* sgr = sg + threadIdx.x * 37;
#pragma unroll
        for (int g = 0; g < G; ++g) {
            float a = sBI[g];
#pragma unroll
            for (int o = 0; o < WS; ++o) a = fmaf(xs[o], sWih[g * WS + o], a);
            sgr[g] = a;
        }
        __syncthreads();

        float4* dst  = g_gi  + ((size_t)k * Bn + bbase) * WS;
        float4* dst2 = g_gi2 + ((size_t)k * Bn + bbase) * WS;
        for (int i = threadIdx.x; i < 256 * WS; i += 256) {
            int bl = i / WS;
            int j = i - bl * WS;
            const float* s = sg + bl * 37;
            float r = s[j], z = s[12 + j], n = s[24 + j];
            dst[i]  = make_float4(0.5f * r, 0.5f * z, -SCL2 * n, 0.0f);
            float pr = spg[j], pz = spg[12 + j], pn = spg[24 + j];
            dst2[i] = make_float4(0.5f * (r + pr), 0.5f * (z + pz),
                                  -SCL2 * (n + pn), 0.0f);
        }
        return;
    }

    // ------------------- weff fold (k = blockIdx-640) -------------------
    {
        float* w2s = sraw;
        int k = blockIdx.x - 640;
        const float4* W24 = (const float4*)(dec_W2 + (size_t)k * DH * WS);
        float4* w2s4 = (float4*)w2s;
        for (int i = threadIdx.x; i < DH * WS / 4; i += 256) w2s4[i] = W24[i];
        __syncthreads();

        float* wdecF = (float*)g_wdec;        // [k][j][16] floats
        int t = threadIdx.x;
        if (t < 144) {
            int d = t / WS, o = t - (t / WS) * WS;
            const float4* w14 = (const float4*)(dec_W1 + ((size_t)k * WS + d) * DH);
            float a0 = 0.f, a1 = 0.f, a2 = 0.f, a3 = 0.f;
            float a4 = 0.f, a5 = 0.f, a6 = 0.f, a7 = 0.f;
            for (int q = 0; q < DH / 4; q += 2) {
                float4 u = w14[q], v = w14[q + 1];
                int h = q * 4;
                a0 = fmaf(u.x, w2s[(h + 0) * WS + o], a0);
                a1 = fmaf(u.y, w2s[(h + 1) * WS + o], a1);
                a2 = fmaf(u.z, w2s[(h + 2) * WS + o], a2);
                a3 = fmaf(u.w, w2s[(h + 3) * WS + o], a3);
                a4 = fmaf(v.x, w2s[(h + 4) * WS + o], a4);
                a5 = fmaf(v.y, w2s[(h + 5) * WS + o], a5);
                a6 = fmaf(v.z, w2s[(h + 6) * WS + o], a6);
                a7 = fmaf(v.w, w2s[(h + 7) * WS + o], a7);
            }
            wdecF[((size_t)k * WS + o) * 16 + d] =
                ((a0 + a1) + (a2 + a3)) + ((a4 + a5) + (a6 + a7));
        } else if (t < 156) {
            int o = t - 144;
            const float4* b14 = (const float4*)(dec_b1 + (size_t)k * DH);
            float a0 = dec_b2[k * WS + o], a1 = 0.f, a2 = 0.f, a3 = 0.f;
            for (int q = 0; q < DH / 4; ++q) {
                float4 u = b14[q];
                int h = q * 4;
                a0 = fmaf(u.x, w2s[(h + 0) * WS + o], a0);
                a1 = fmaf(u.y, w2s[(h + 1) * WS + o], a1);
                a2 = fmaf(u.z, w2s[(h + 2) * WS + o], a2);
                a3 = fmaf(u.w, w2s[(h + 3) * WS + o], a3);
            }
            wdecF[((size_t)k * WS + o) * 16 + 12] = (a0 + a1) + (a2 + a3);
        }
    }
}

// ---------------------------------------------------------------------------
// RNN + fused decoder. R8 structure: one row per 16-lane group, 2 rows/warp
// SIMD. Gate sigmoids via tanh.approx (σ(x)=0.5·tanh(x/2)+0.5, scales folded);
// n-path on accurate ex2/rcp. Phase 2 reads pe-folded g_gi2 (no pegi smem).
// Decoder weights staged in 120 KB dynamic smem.
// ---------------------------------------------------------------------------
__device__ __forceinline__ void bcast(float h, float* hx) {
#pragma unroll
    for (int i = 0; i < 12; ++i) hx[i] = __shfl_sync(0xffffffffu, h, i, 16);
}

__device__ __forceinline__ float gates(const float* hx, float gr, float gz,
                                       float gn, float bnp,
                                       const float* wr, const float* wz,
                                       const float* wn, float h) {
    float a0 = gr, a1 = 0.f, b0 = gz, b1 = 0.f, c0 = bnp, c1 = 0.f;
#pragma unroll
    for (int i = 0; i < 12; i += 2) {
        a0 = fmaf(wr[i], hx[i], a0); a1 = fmaf(wr[i + 1], hx[i + 1], a1);
        b0 = fmaf(wz[i], hx[i], b0); b1 = fmaf(wz[i + 1], hx[i + 1], b1);
        c0 = fmaf(wn[i], hx[i], c0); c1 = fmaf(wn[i + 1], hx[i + 1], c1);
    }
    float r = fmaf(0.5f, ftanh(a0 + a1), 0.5f);        // sigmoid
    float z = fmaf(0.5f, ftanh(b0 + b1), 0.5f);
    float n = fmaf(2.0f, frcp(1.0f + fex2(fmaf(r, c0 + c1, gn))), -1.0f);
    return fmaf(z, h - n, n);
}

__device__ __forceinline__ float decacc(const float* hx, const float4* wb) {
    float4 w0 = wb[0], w1 = wb[1], w2 = wb[2];
    float be = wb[3].x;
    float s0 = be, s1 = 0.f, s2 = 0.f, s3 = 0.f;
    s0 = fmaf(hx[0], w0.x, s0); s1 = fmaf(hx[1], w0.y, s1);
    s2 = fmaf(hx[2], w0.z, s2); s3 = fmaf(hx[3], w0.w, s3);
    s0 = fmaf(hx[4], w1.x, s0); s1 = fmaf(hx[5], w1.y, s1);
    s2 = fmaf(hx[6], w1.z, s2); s3 = fmaf(hx[7], w1.w, s3);
    s0 = fmaf(hx[8], w2.x, s0); s1 = fmaf(hx[9], w2.y, s1);
    s2 = fmaf(hx[10], w2.z, s2); s3 = fmaf(hx[11], w2.w, s3);
    return (s0 + s1) + (s2 + s3);
}

extern __shared__ float4 s_wdec[];   // Kseg*WS*4 float4 = 120 KB

__global__ void __launch_bounds__(128) rnn_kernel(const float* __restrict__ Whh,
                                                  const float* __restrict__ bhh,
                                                  float* __restrict__ out) {
    int lane16 = threadIdx.x & 15;
    int row = blockIdx.x * 8 + (threadIdx.x >> 4);   // 0..1023
    bool act = (lane16 < WS);
    int j = act ? lane16 : (WS - 1);

    float wr[12], wz[12], wn[12];
#pragma unroll
    for (int i = 0; i < 12; ++i) {
        wr[i] = 0.5f * Whh[j * 12 + i];
        wz[i] = 0.5f * Whh[(12 + j) * 12 + i];
        wn[i] = -SCL2 * Whh[(24 + j) * 12 + i];
    }
    float bnp = -SCL2 * bhh[24 + j];

    for (int i = threadIdx.x; i < Kseg * WS * 4; i += 128) s_wdec[i] = g_wdec[i];
    __syncthreads();

    const float4* pA = g_gi  + (size_t)row * WS + j;
    const float4* pB = g_gi2 + (size_t)row * WS + j;
    float h = 0.0f;
    float4 a0, a1, a2, a3;
    const float4* q;

    // ---------------- phase 1: first GRU (keep only final h) ---------------
    a0 = pA[0];
    a1 = pA[STR4];
    a2 = pA[2 * STR4];
    a3 = pA[3 * STR4];
    q = pA + 4 * STR4;
    for (int t = 0; t < Kseg; t += 4) {
        float hx[12];
        bcast(h, hx); h = gates(hx, a0.x, a0.y, a0.z, bnp, wr, wz, wn, h);
        a0 = q[0];
        bcast(h, hx); h = gates(hx, a1.x, a1.y, a1.z, bnp, wr, wz, wn, h);
        a1 = q[STR4];
        bcast(h, hx); h = gates(hx, a2.x, a2.y, a2.z, bnp, wr, wz, wn, h);
        a2 = q[2 * STR4];
        bcast(h, hx); h = gates(hx, a3.x, a3.y, a3.z, bnp, wr, wz, wn, h);
        a3 = q[3 * STR4];
        q += 4 * STR4;
    }

    // ---------------- phase 2: second GRU + fused decoder -------------------
    float* outp = out + (size_t)row * 1920 + j;
    const float4* wj = s_wdec + (size_t)j * 4;   // + t*48 per step

    a0 = pB[0];
    a1 = pB[STR4];
    a2 = pB[2 * STR4];
    a3 = pB[3 * STR4];
    q = pB + 4 * STR4;

#define STEP2(AREG, TT, QOFF)                                               \
    {                                                                       \
        float hx[12];                                                       \
        bcast(h, hx);                                                       \
        if (act && (TT) > 0) {                                              \
            float oa = decacc(hx, wj + (size_t)((TT) - 1) * 48);            \
            outp[((TT) - 1) * 12] = oa;                                     \
        }                                                                   \
        h = gates(hx, AREG.x, AREG.y, AREG.z, bnp, wr, wz, wn, h);          \
        AREG = q[QOFF];                                                     \
    }

    for (int t = 0; t < Kseg; t += 4) {
        STEP2(a0, t + 0, 0);
        STEP2(a1, t + 1, STR4);
        STEP2(a2, t + 2, 2 * STR4);
        STEP2(a3, t + 3, 3 * STR4);
        q += 4 * STR4;
    }
#undef STEP2

    // tail: out for t = Kseg-1
    {
        float hx[12];
        bcast(h, hx);
        if (act) {
            float oa = decacc(hx, wj + (size_t)(Kseg - 1) * 48);
            outp[(Kseg - 1) * 12] = oa;
        }
    }
}

// ---------------------------------------------------------------------------
extern "C" void kernel_launch(void* const* d_in, const int* in_sizes, int n_in,
                              void* d_out, int out_size) {
    const float* x     = (const float*)d_in[0];
    const float* enc_W = (const float*)d_in[1];
    const float* enc_b = (const float*)d_in[2];
    const float* Wih   = (const float*)d_in[3];
    const float* Whh   = (const float*)d_in[4];
    const float* bih   = (const float*)d_in[5];
    const float* bhh   = (const float*)d_in[6];
    const float* dW1   = (const float*)d_in[7];
    const float* db1   = (const float*)d_in[8];
    const float* dW2   = (const float*)d_in[9];
    const float* db2   = (const float*)d_in[10];
    float* out = (float*)d_out;

    const int RNN_SMEM = Kseg * WS * 4 * 16;   // 122880 B
    cudaFuncSetAttribute(rnn_kernel,
                         cudaFuncAttributeMaxDynamicSharedMemorySize,
                         RNN_SMEM);

    prep_kernel<<<800, 256>>>(x, enc_W, enc_b, Wih, bih, bhh,
                              dW1, db1, dW2, db2);
    rnn_kernel<<<128, 128, RNN_SMEM>>>(Whh, bhh, out);
}

// round 11
// speedup vs baseline: 1.3156x; 1.3150x over previous
#include <cuda_runtime.h>

#define Bn   1024
#define Kseg 160
#define WS   12
#define G    36
#define DH   1024
#define TPAD 164            // Kseg + 4 prefetch pad
#define STR4 (Bn * WS)      // float4 stride between t slots

// Scratch (static device globals — no allocation)
__device__ float4 g_gi[TPAD * Bn * WS];    // [t][b][j] = {0.5*r, 0.5*z, n_raw, 0}
__device__ float4 g_pegi4[Kseg * WS];      // [k][j] = {0.5*pr, 0.5*pz, pn_raw, 0}
__device__ float4 g_wdec[Kseg * WS * 4];   // [k][j][4]: w0..3,w4..7,w8..11,{beff,..}

// Warp-uniform weights -> LDCU path (separate uniform port, no LSU contention)
__constant__ float cWih[G * WS];
__constant__ float cbih[G];
__constant__ float cbhh[G];

__device__ __forceinline__ float ftanh(float x) {
    float y; asm("tanh.approx.f32 %0, %1;" : "=f"(y) : "f"(x)); return y;
}

// ---------------------------------------------------------------------------
// Prep kernel: blocks 0..639 = encoder + gi, 640..799 = weff fold, 800 = pegi.
// ---------------------------------------------------------------------------
__global__ void __launch_bounds__(256) prep_kernel(
        const float* __restrict__ x,
        const float* __restrict__ enc_W,
        const float* __restrict__ enc_b,
        const float* __restrict__ dec_W1,
        const float* __restrict__ dec_b1,
        const float* __restrict__ dec_W2,
        const float* __restrict__ dec_b2) {
    __shared__ float sraw[DH * WS];   // 48 KB, reused by branches

    if (blockIdx.x < 640) {
        // ------------------- encoder + gi -------------------
        float* sEW = sraw;            // 144
        float* sEB = sraw + 144;      // 12
        float* sg  = sraw + 192;      // 256*37 = 9472
        int k = blockIdx.x >> 2;
        int bbase = (blockIdx.x & 3) << 8;
        int b = bbase + threadIdx.x;

        {
            int t = threadIdx.x;
            if (t < WS * WS) sEW[t] = enc_W[k * (WS * WS) + t];
            if (t < WS) sEB[t] = enc_b[k * WS + t];
        }
        __syncthreads();

        const float4* xr4 = (const float4*)(x + (size_t)b * 1920 + k * WS);
        float4 x0 = xr4[0], x1 = xr4[1], x2 = xr4[2];
        float xv[WS] = {x0.x, x0.y, x0.z, x0.w, x1.x, x1.y, x1.z, x1.w,
                        x2.x, x2.y, x2.z, x2.w};

        float xs[WS];
#pragma unroll
        for (int o = 0; o < WS; ++o) {
            float a = sEB[o];
#pragma unroll
            for (int i = 0; i < WS; ++i) a = fmaf(xv[i], sEW[i * WS + o], a);
            xs[o] = fmaxf(a, 0.0f);
        }

        float* sgr = sg + threadIdx.x * 37;
#pragma unroll
        for (int g = 0; g < G; ++g) {
            float a = cbih[g] + ((g < 24) ? cbhh[g] : 0.0f);   // fold bhh_r,z
#pragma unroll
            for (int o = 0; o < WS; ++o) a = fmaf(xs[o], cWih[g * WS + o], a);
            sgr[g] = a;
        }
        __syncthreads();

        float4* dst = g_gi + ((size_t)k * Bn + bbase) * WS;
        for (int i = threadIdx.x; i < 256 * WS; i += 256) {
            int bl = i / WS;
            int j = i - bl * WS;
            const float* s = sg + bl * 37;
            dst[i] = make_float4(0.5f * s[j], 0.5f * s[12 + j], s[24 + j], 0.0f);
        }
        return;
    }

    if (blockIdx.x == 800) {
        // ------------------- pegi table -------------------
        int k = threadIdx.x;
        if (k >= Kseg) return;
        float pe[WS];
        const float c = -9.210340371976184f / 12.0f;   // -ln(10000)/d
#pragma unroll
        for (int j = 0; j < 6; ++j) {
            float div = expf(c * (float)(2 * j));
            float ang = (float)k * div;
            pe[2 * j]     = sinf(ang);
            pe[2 * j + 1] = cosf(ang);
        }
        float ch = sinf((float)k);
#pragma unroll
        for (int o = 0; o < WS; ++o) pe[o] += ch;
        float pg[G];
#pragma unroll
        for (int g = 0; g < G; ++g) {
            float a = 0.0f;
#pragma unroll
            for (int o = 0; o < WS; ++o) a = fmaf(pe[o], cWih[g * WS + o], a);
            pg[g] = a;
        }
#pragma unroll
        for (int j = 0; j < WS; ++j)
            g_pegi4[k * WS + j] = make_float4(0.5f * pg[j], 0.5f * pg[12 + j],
                                              pg[24 + j], 0.0f);
        return;
    }

    // ------------------- weff fold (k = blockIdx-640) -------------------
    {
        float* w2s = sraw;
        int k = blockIdx.x - 640;
        const float4* W24 = (const float4*)(dec_W2 + (size_t)k * DH * WS);
        float4* w2s4 = (float4*)w2s;
        for (int i = threadIdx.x; i < DH * WS / 4; i += 256) w2s4[i] = W24[i];
        __syncthreads();

        float* wdecF = (float*)g_wdec;        // [k][j][16] floats
        int t = threadIdx.x;
        if (t < 144) {
            int d = t / WS, o = t - (t / WS) * WS;
            const float4* w14 = (const float4*)(dec_W1 + ((size_t)k * WS + d) * DH);
            float a0 = 0.f, a1 = 0.f, a2 = 0.f, a3 = 0.f;
            float a4 = 0.f, a5 = 0.f, a6 = 0.f, a7 = 0.f;
            for (int q = 0; q < DH / 4; q += 2) {
                float4 u = w14[q], v = w14[q + 1];
                int h = q * 4;
                a0 = fmaf(u.x, w2s[(h + 0) * WS + o], a0);
                a1 = fmaf(u.y, w2s[(h + 1) * WS + o], a1);
                a2 = fmaf(u.z, w2s[(h + 2) * WS + o], a2);
                a3 = fmaf(u.w, w2s[(h + 3) * WS + o], a3);
                a4 = fmaf(v.x, w2s[(h + 4) * WS + o], a4);
                a5 = fmaf(v.y, w2s[(h + 5) * WS + o], a5);
                a6 = fmaf(v.z, w2s[(h + 6) * WS + o], a6);
                a7 = fmaf(v.w, w2s[(h + 7) * WS + o], a7);
            }
            wdecF[((size_t)k * WS + o) * 16 + d] =
                ((a0 + a1) + (a2 + a3)) + ((a4 + a5) + (a6 + a7));
        } else if (t < 156) {
            int o = t - 144;
            const float4* b14 = (const float4*)(dec_b1 + (size_t)k * DH);
            float a0 = dec_b2[k * WS + o], a1 = 0.f, a2 = 0.f, a3 = 0.f;
            for (int q = 0; q < DH / 4; ++q) {
                float4 u = b14[q];
                int h = q * 4;
                a0 = fmaf(u.x, w2s[(h + 0) * WS + o], a0);
                a1 = fmaf(u.y, w2s[(h + 1) * WS + o], a1);
                a2 = fmaf(u.z, w2s[(h + 2) * WS + o], a2);
                a3 = fmaf(u.w, w2s[(h + 3) * WS + o], a3);
            }
            wdecF[((size_t)k * WS + o) * 16 + 12] = (a0 + a1) + (a2 + a3);
        }
    }
}

// ---------------------------------------------------------------------------
// RNN + fused decoder. R8 structure: one row per 16-lane group, 2 rows/warp
// SIMD; pegi + wdec in 150 KB dynamic smem; phase 2 re-reads L2-warm g_gi.
// ALL activations via tanh.approx: sigma(x) = 0.5 + 0.5*tanh(x/2) (0.5 folded
// into prescales), n = tanh(raw arg) directly.
// ---------------------------------------------------------------------------
__device__ __forceinline__ void bcast(float h, float* hx) {
#pragma unroll
    for (int i = 0; i < 12; ++i) hx[i] = __shfl_sync(0xffffffffu, h, i, 16);
}

__device__ __forceinline__ float gates(const float* hx, float gr, float gz,
                                       float gn, float bnp,
                                       const float* wr, const float* wz,
                                       const float* wn, float h) {
    float a0 = gr, a1 = 0.f, b0 = gz, b1 = 0.f, c0 = bnp, c1 = 0.f;
#pragma unroll
    for (int i = 0; i < 12; i += 2) {
        a0 = fmaf(wr[i], hx[i], a0); a1 = fmaf(wr[i + 1], hx[i + 1], a1);
        b0 = fmaf(wz[i], hx[i], b0); b1 = fmaf(wz[i + 1], hx[i + 1], b1);
        c0 = fmaf(wn[i], hx[i], c0); c1 = fmaf(wn[i + 1], hx[i + 1], c1);
    }
    float r = fmaf(0.5f, ftanh(a0 + a1), 0.5f);        // sigmoid
    float z = fmaf(0.5f, ftanh(b0 + b1), 0.5f);
    float n = ftanh(fmaf(r, c0 + c1, gn));             // direct tanh
    return fmaf(z, h - n, n);
}

__device__ __forceinline__ float decacc(const float* hx, const float4* wb) {
    float4 w0 = wb[0], w1 = wb[1], w2 = wb[2];
    float be = wb[3].x;
    float s0 = be, s1 = 0.f, s2 = 0.f, s3 = 0.f;
    s0 = fmaf(hx[0], w0.x, s0); s1 = fmaf(hx[1], w0.y, s1);
    s2 = fmaf(hx[2], w0.z, s2); s3 = fmaf(hx[3], w0.w, s3);
    s0 = fmaf(hx[4], w1.x, s0); s1 = fmaf(hx[5], w1.y, s1);
    s2 = fmaf(hx[6], w1.z, s2); s3 = fmaf(hx[7], w1.w, s3);
    s0 = fmaf(hx[8], w2.x, s0); s1 = fmaf(hx[9], w2.y, s1);
    s2 = fmaf(hx[10], w2.z, s2); s3 = fmaf(hx[11], w2.w, s3);
    return (s0 + s1) + (s2 + s3);
}

extern __shared__ float4 s_dyn[];   // [0..1919]: pegis, [1920..9599]: wdec

__global__ void __launch_bounds__(128) rnn_kernel(const float* __restrict__ Whh,
                                                  const float* __restrict__ bhh,
                                                  float* __restrict__ out) {
    float4* pegis = s_dyn;                     // 30 KB
    float4* wsm   = s_dyn + Kseg * WS;         // 120 KB
    int lane16 = threadIdx.x & 15;
    int row = blockIdx.x * 8 + (threadIdx.x >> 4);   // 0..1023
    bool act = (lane16 < WS);
    int j = act ? lane16 : (WS - 1);

    float wr[12], wz[12], wn[12];
#pragma unroll
    for (int i = 0; i < 12; ++i) {
        wr[i] = 0.5f * Whh[j * 12 + i];
        wz[i] = 0.5f * Whh[(12 + j) * 12 + i];
        wn[i] = Whh[(24 + j) * 12 + i];
    }
    float bnp = bhh[24 + j];

    for (int i = threadIdx.x; i < Kseg * WS; i += 128) pegis[i] = g_pegi4[i];
    for (int i = threadIdx.x; i < Kseg * WS * 4; i += 128) wsm[i] = g_wdec[i];
    __syncthreads();

    const float4* pA = g_gi + (size_t)row * WS + j;
    float h = 0.0f;
    float4 a0, a1, a2, a3;
    const float4* q;

    // ---------------- phase 1: first GRU (keep only final h) ---------------
    a0 = pA[0];
    a1 = pA[STR4];
    a2 = pA[2 * STR4];
    a3 = pA[3 * STR4];
    q = pA + 4 * STR4;
    for (int t = 0; t < Kseg; t += 4) {
        float hx[12];
        bcast(h, hx); h = gates(hx, a0.x, a0.y, a0.z, bnp, wr, wz, wn, h);
        a0 = q[0];
        bcast(h, hx); h = gates(hx, a1.x, a1.y, a1.z, bnp, wr, wz, wn, h);
        a1 = q[STR4];
        bcast(h, hx); h = gates(hx, a2.x, a2.y, a2.z, bnp, wr, wz, wn, h);
        a2 = q[2 * STR4];
        bcast(h, hx); h = gates(hx, a3.x, a3.y, a3.z, bnp, wr, wz, wn, h);
        a3 = q[3 * STR4];
        q += 4 * STR4;
    }

    // ---------------- phase 2: second GRU + fused decoder -------------------
    float* outp = out + (size_t)row * 1920 + j;
    const float4* wj = wsm + (size_t)j * 4;    // + t*48 per step

    a0 = pA[0];
    a1 = pA[STR4];
    a2 = pA[2 * STR4];
    a3 = pA[3 * STR4];
    q = pA + 4 * STR4;
    const float4* pg = pegis + j;

#define STEP2(AREG, PV, TT, QOFF)                                           \
    {                                                                       \
        float hx[12];                                                       \
        bcast(h, hx);                                                       \
        if (act && (TT) > 0) {                                              \
            float oa = decacc(hx, wj + (size_t)((TT) - 1) * 48);            \
            outp[((TT) - 1) * 12] = oa;                                     \
        }                                                                   \
        h = gates(hx, AREG.x + PV.x, AREG.y + PV.y, AREG.z + PV.z, bnp,     \
                  wr, wz, wn, h);                                           \
        AREG = q[QOFF];                                                     \
    }

    for (int t = 0; t < Kseg; t += 4) {
        float4 p0 = pg[0], p1 = pg[WS], p2 = pg[2 * WS], p3 = pg[3 * WS];
        pg += 4 * WS;
        STEP2(a0, p0, t + 0, 0);
        STEP2(a1, p1, t + 1, STR4);
        STEP2(a2, p2, t + 2, 2 * STR4);
        STEP2(a3, p3, t + 3, 3 * STR4);
        q += 4 * STR4;
    }
#undef STEP2

    // tail: out for t = Kseg-1
    {
        float hx[12];
        bcast(h, hx);
        if (act) {
            float oa = decacc(hx, wj + (size_t)(Kseg - 1) * 48);
            outp[(Kseg - 1) * 12] = oa;
        }
    }
}

// ---------------------------------------------------------------------------
extern "C" void kernel_launch(void* const* d_in, const int* in_sizes, int n_in,
                              void* d_out, int out_size) {
    const float* x     = (const float*)d_in[0];
    const float* enc_W = (const float*)d_in[1];
    const float* enc_b = (const float*)d_in[2];
    const float* Wih   = (const float*)d_in[3];
    const float* Whh   = (const float*)d_in[4];
    const float* bih   = (const float*)d_in[5];
    const float* bhh   = (const float*)d_in[6];
    const float* dW1   = (const float*)d_in[7];
    const float* db1   = (const float*)d_in[8];
    const float* dW2   = (const float*)d_in[9];
    const float* db2   = (const float*)d_in[10];
    float* out = (float*)d_out;

    const int RNN_SMEM = Kseg * WS * 5 * 16;   // 153600 B
    cudaFuncSetAttribute(rnn_kernel,
                         cudaFuncAttributeMaxDynamicSharedMemorySize,
                         RNN_SMEM);

    // Device-to-device async copies into __constant__ (graph-capturable)
    cudaMemcpyToSymbolAsync(cWih, Wih, G * WS * sizeof(float), 0,
                            cudaMemcpyDeviceToDevice);
    cudaMemcpyToSymbolAsync(cbih, bih, G * sizeof(float), 0,
                            cudaMemcpyDeviceToDevice);
    cudaMemcpyToSymbolAsync(cbhh, bhh, G * sizeof(float), 0,
                            cudaMemcpyDeviceToDevice);

    prep_kernel<<<801, 256>>>(x, enc_W, enc_b, dW1, db1, dW2, db2);
    rnn_kernel<<<128, 128, RNN_SMEM>>>(Whh, bhh, out);
}

// round 12
// speedup vs baseline: 1.3881x; 1.0551x over previous
#include <cuda_runtime.h>

#define Bn   1024
#define Kseg 160
#define WS   12
#define G    36
#define DH   1024
#define TPAD 164            // Kseg + 4 prefetch pad
#define STR4 (Bn * WS)      // float4 stride between t slots

typedef unsigned long long u64;

// Scratch (static device globals — no allocation)
__device__ float4 g_gi[TPAD * Bn * WS];    // [t][b][j] = {0.5*r, 0.5*z, n_raw, 0}
__device__ float4 g_pegi4[Kseg * WS];      // [k][j] = {0.5*pr, 0.5*pz, pn_raw, 0}
__device__ float4 g_wdec[Kseg * WS * 4];   // [k][j][4]: w0..3,w4..7,w8..11,{beff,..}

// Warp-uniform weights -> constant path
__constant__ float cWih[G * WS];
__constant__ float cbih[G];
__constant__ float cbhh[G];

__device__ __forceinline__ float ftanh(float x) {
    float y; asm("tanh.approx.f32 %0, %1;" : "=f"(y) : "f"(x)); return y;
}
__device__ __forceinline__ u64 pk(float lo, float hi) {
    u64 r; asm("mov.b64 %0, {%1, %2};" : "=l"(r) : "f"(lo), "f"(hi)); return r;
}
__device__ __forceinline__ void upk(u64 v, float& lo, float& hi) {
    asm("mov.b64 {%0, %1}, %2;" : "=f"(lo), "=f"(hi) : "l"(v));
}
__device__ __forceinline__ u64 ffma2(u64 a, u64 b, u64 c) {
    u64 d; asm("fma.rn.f32x2 %0, %1, %2, %3;" : "=l"(d) : "l"(a), "l"(b), "l"(c));
    return d;
}

// ---------------------------------------------------------------------------
// Prep kernel: blocks 0..639 = encoder + gi, 640..799 = weff fold, 800 = pegi.
// ---------------------------------------------------------------------------
__global__ void __launch_bounds__(256) prep_kernel(
        const float* __restrict__ x,
        const float* __restrict__ enc_W,
        const float* __restrict__ enc_b,
        const float* __restrict__ dec_W1,
        const float* __restrict__ dec_b1,
        const float* __restrict__ dec_W2,
        const float* __restrict__ dec_b2) {
    __shared__ float sraw[DH * WS];   // 48 KB, reused by branches

    if (blockIdx.x < 640) {
        // ------------------- encoder + gi -------------------
        float* sEW = sraw;            // 144
        float* sEB = sraw + 144;      // 12
        float* sg  = sraw + 192;      // 256*37 = 9472
        int k = blockIdx.x >> 2;
        int bbase = (blockIdx.x & 3) << 8;
        int b = bbase + threadIdx.x;

        {
            int t = threadIdx.x;
            if (t < WS * WS) sEW[t] = enc_W[k * (WS * WS) + t];
            if (t < WS) sEB[t] = enc_b[k * WS + t];
        }
        __syncthreads();

        const float4* xr4 = (const float4*)(x + (size_t)b * 1920 + k * WS);
        float4 x0 = xr4[0], x1 = xr4[1], x2 = xr4[2];
        float xv[WS] = {x0.x, x0.y, x0.z, x0.w, x1.x, x1.y, x1.z, x1.w,
                        x2.x, x2.y, x2.z, x2.w};

        float xs[WS];
#pragma unroll
        for (int o = 0; o < WS; ++o) {
            float a = sEB[o];
#pragma unroll
            for (int i = 0; i < WS; ++i) a = fmaf(xv[i], sEW[i * WS + o], a);
            xs[o] = fmaxf(a, 0.0f);
        }

        float* sgr = sg + threadIdx.x * 37;
#pragma unroll
        for (int g = 0; g < G; ++g) {
            float a = cbih[g] + ((g < 24) ? cbhh[g] : 0.0f);   // fold bhh_r,z
#pragma unroll
            for (int o = 0; o < WS; ++o) a = fmaf(xs[o], cWih[g * WS + o], a);
            sgr[g] = a;
        }
        __syncthreads();

        float4* dst = g_gi + ((size_t)k * Bn + bbase) * WS;
        for (int i = threadIdx.x; i < 256 * WS; i += 256) {
            int bl = i / WS;
            int j = i - bl * WS;
            const float* s = sg + bl * 37;
            dst[i] = make_float4(0.5f * s[j], 0.5f * s[12 + j], s[24 + j], 0.0f);
        }
        return;
    }

    if (blockIdx.x == 800) {
        // ------------------- pegi table -------------------
        int k = threadIdx.x;
        if (k >= Kseg) return;
        float pe[WS];
        const float c = -9.210340371976184f / 12.0f;   // -ln(10000)/d
#pragma unroll
        for (int j = 0; j < 6; ++j) {
            float div = expf(c * (float)(2 * j));
            float ang = (float)k * div;
            pe[2 * j]     = sinf(ang);
            pe[2 * j + 1] = cosf(ang);
        }
        float ch = sinf((float)k);
#pragma unroll
        for (int o = 0; o < WS; ++o) pe[o] += ch;
        float pg[G];
#pragma unroll
        for (int g = 0; g < G; ++g) {
            float a = 0.0f;
#pragma unroll
            for (int o = 0; o < WS; ++o) a = fmaf(pe[o], cWih[g * WS + o], a);
            pg[g] = a;
        }
#pragma unroll
        for (int j = 0; j < WS; ++j)
            g_pegi4[k * WS + j] = make_float4(0.5f * pg[j], 0.5f * pg[12 + j],
                                              pg[24 + j], 0.0f);
        return;
    }

    // ------------------- weff fold (k = blockIdx-640) -------------------
    {
        float* w2s = sraw;
        int k = blockIdx.x - 640;
        const float4* W24 = (const float4*)(dec_W2 + (size_t)k * DH * WS);
        float4* w2s4 = (float4*)w2s;
        for (int i = threadIdx.x; i < DH * WS / 4; i += 256) w2s4[i] = W24[i];
        __syncthreads();

        float* wdecF = (float*)g_wdec;        // [k][j][16] floats
        int t = threadIdx.x;
        if (t < 144) {
            int d = t / WS, o = t - (t / WS) * WS;
            const float4* w14 = (const float4*)(dec_W1 + ((size_t)k * WS + d) * DH);
            float a0 = 0.f, a1 = 0.f, a2 = 0.f, a3 = 0.f;
            float a4 = 0.f, a5 = 0.f, a6 = 0.f, a7 = 0.f;
            for (int q = 0; q < DH / 4; q += 2) {
                float4 u = w14[q], v = w14[q + 1];
                int h = q * 4;
                a0 = fmaf(u.x, w2s[(h + 0) * WS + o], a0);
                a1 = fmaf(u.y, w2s[(h + 1) * WS + o], a1);
                a2 = fmaf(u.z, w2s[(h + 2) * WS + o], a2);
                a3 = fmaf(u.w, w2s[(h + 3) * WS + o], a3);
                a4 = fmaf(v.x, w2s[(h + 4) * WS + o], a4);
                a5 = fmaf(v.y, w2s[(h + 5) * WS + o], a5);
                a6 = fmaf(v.z, w2s[(h + 6) * WS + o], a6);
                a7 = fmaf(v.w, w2s[(h + 7) * WS + o], a7);
            }
            wdecF[((size_t)k * WS + o) * 16 + d] =
                ((a0 + a1) + (a2 + a3)) + ((a4 + a5) + (a6 + a7));
        } else if (t < 156) {
            int o = t - 144;
            const float4* b14 = (const float4*)(dec_b1 + (size_t)k * DH);
            float a0 = dec_b2[k * WS + o], a1 = 0.f, a2 = 0.f, a3 = 0.f;
            for (int q = 0; q < DH / 4; ++q) {
                float4 u = b14[q];
                int h = q * 4;
                a0 = fmaf(u.x, w2s[(h + 0) * WS + o], a0);
                a1 = fmaf(u.y, w2s[(h + 1) * WS + o], a1);
                a2 = fmaf(u.z, w2s[(h + 2) * WS + o], a2);
                a3 = fmaf(u.w, w2s[(h + 3) * WS + o], a3);
            }
            wdecF[((size_t)k * WS + o) * 16 + 12] = (a0 + a1) + (a2 + a3);
        }
    }
}

// ---------------------------------------------------------------------------
// RNN + fused decoder. R11 structure, gate math in packed fma.rn.f32x2:
// h-pairs (h_2m, h_2m+1) packed once per step; r/z/n dots = 18 FFMA2,
// decoder dot = 6 FFMA2 on wdec's native pair layout.
// ---------------------------------------------------------------------------
__device__ __forceinline__ void bcast2(float h, u64* hp) {
#pragma unroll
    for (int m = 0; m < 6; ++m) {
        float h0 = __shfl_sync(0xffffffffu, h, 2 * m, 16);
        float h1 = __shfl_sync(0xffffffffu, h, 2 * m + 1, 16);
        hp[m] = pk(h0, h1);
    }
}

__device__ __forceinline__ float gates2(const u64* hp, float gr, float gz,
                                        float gn, float bnp,
                                        const u64* wR, const u64* wZ,
                                        const u64* wN, float h) {
    u64 aR = pk(gr, 0.f), aZ = pk(gz, 0.f), aN = pk(bnp, 0.f);
#pragma unroll
    for (int m = 0; m < 6; ++m) {
        aR = ffma2(wR[m], hp[m], aR);
        aZ = ffma2(wZ[m], hp[m], aZ);
        aN = ffma2(wN[m], hp[m], aN);
    }
    float rl, rh, zl, zh, nl, nh;
    upk(aR, rl, rh); upk(aZ, zl, zh); upk(aN, nl, nh);
    float r = fmaf(0.5f, ftanh(rl + rh), 0.5f);        // sigmoid
    float z = fmaf(0.5f, ftanh(zl + zh), 0.5f);
    float n = ftanh(fmaf(r, nl + nh, gn));             // direct tanh
    return fmaf(z, h - n, n);
}

__device__ __forceinline__ float decacc2(const u64* hp, const float4* wb) {
    const u64* w = (const u64*)wb;          // 6 packed pairs, then {beff,..}
    u64 acc = pk(wb[3].x, 0.f);
#pragma unroll
    for (int m = 0; m < 6; ++m) acc = ffma2(w[m], hp[m], acc);
    float lo, hi; upk(acc, lo, hi);
    return lo + hi;
}

extern __shared__ float4 s_dyn[];   // [0..1919]: pegis, [1920..9599]: wdec

__global__ void __launch_bounds__(128) rnn_kernel(const float* __restrict__ Whh,
                                                  const float* __restrict__ bhh,
                                                  float* __restrict__ out) {
    float4* pegis = s_dyn;                     // 30 KB
    float4* wsm   = s_dyn + Kseg * WS;         // 120 KB
    int lane16 = threadIdx.x & 15;
    int row = blockIdx.x * 8 + (threadIdx.x >> 4);   // 0..1023
    bool act = (lane16 < WS);
    int j = act ? lane16 : (WS - 1);

    u64 wR[6], wZ[6], wN[6];
#pragma unroll
    for (int m = 0; m < 6; ++m) {
        wR[m] = pk(0.5f * Whh[j * 12 + 2 * m],        0.5f * Whh[j * 12 + 2 * m + 1]);
        wZ[m] = pk(0.5f * Whh[(12 + j) * 12 + 2 * m], 0.5f * Whh[(12 + j) * 12 + 2 * m + 1]);
        wN[m] = pk(Whh[(24 + j) * 12 + 2 * m],        Whh[(24 + j) * 12 + 2 * m + 1]);
    }
    float bnp = bhh[24 + j];

    for (int i = threadIdx.x; i < Kseg * WS; i += 128) pegis[i] = g_pegi4[i];
    for (int i = threadIdx.x; i < Kseg * WS * 4; i += 128) wsm[i] = g_wdec[i];
    __syncthreads();

    const float4* pA = g_gi + (size_t)row * WS + j;
    float h = 0.0f;
    float4 a0, a1, a2, a3;
    const float4* q;

    // ---------------- phase 1: first GRU (keep only final h) ---------------
    a0 = pA[0];
    a1 = pA[STR4];
    a2 = pA[2 * STR4];
    a3 = pA[3 * STR4];
    q = pA + 4 * STR4;
    for (int t = 0; t < Kseg; t += 4) {
        u64 hp[6];
        bcast2(h, hp); h = gates2(hp, a0.x, a0.y, a0.z, bnp, wR, wZ, wN, h);
        a0 = q[0];
        bcast2(h, hp); h = gates2(hp, a1.x, a1.y, a1.z, bnp, wR, wZ, wN, h);
        a1 = q[STR4];
        bcast2(h, hp); h = gates2(hp, a2.x, a2.y, a2.z, bnp, wR, wZ, wN, h);
        a2 = q[2 * STR4];
        bcast2(h, hp); h = gates2(hp, a3.x, a3.y, a3.z, bnp, wR, wZ, wN, h);
        a3 = q[3 * STR4];
        q += 4 * STR4;
    }

    // ---------------- phase 2: second GRU + fused decoder -------------------
    float* outp = out + (size_t)row * 1920 + j;
    const float4* wj = wsm + (size_t)j * 4;    // + t*48 per step

    a0 = pA[0];
    a1 = pA[STR4];
    a2 = pA[2 * STR4];
    a3 = pA[3 * STR4];
    q = pA + 4 * STR4;
    const float4* pg = pegis + j;

#define STEP2(AREG, PV, TT, QOFF)                                           \
    {                                                                       \
        u64 hp[6];                                                          \
        bcast2(h, hp);                                                      \
        if (act && (TT) > 0) {                                              \
            float oa = decacc2(hp, wj + (size_t)((TT) - 1) * 48);           \
            outp[((TT) - 1) * 12] = oa;                                     \
        }                                                                   \
        h = gates2(hp, AREG.x + PV.x, AREG.y + PV.y, AREG.z + PV.z, bnp,    \
                   wR, wZ, wN, h);                                          \
        AREG = q[QOFF];                                                     \
    }

    for (int t = 0; t < Kseg; t += 4) {
        float4 p0 = pg[0], p1 = pg[WS], p2 = pg[2 * WS], p3 = pg[3 * WS];
        pg += 4 * WS;
        STEP2(a0, p0, t + 0, 0);
        STEP2(a1, p1, t + 1, STR4);
        STEP2(a2, p2, t + 2, 2 * STR4);
        STEP2(a3, p3, t + 3, 3 * STR4);
        q += 4 * STR4;
    }
#undef STEP2

    // tail: out for t = Kseg-1
    {
        u64 hp[6];
        bcast2(h, hp);
        if (act) {
            float oa = decacc2(hp, wj + (size_t)(Kseg - 1) * 48);
            outp[(Kseg - 1) * 12] = oa;
        }
    }
}

// ---------------------------------------------------------------------------
extern "C" void kernel_launch(void* const* d_in, const int* in_sizes, int n_in,
                              void* d_out, int out_size) {
    const float* x     = (const float*)d_in[0];
    const float* enc_W = (const float*)d_in[1];
    const float* enc_b = (const float*)d_in[2];
    const float* Wih   = (const float*)d_in[3];
    const float* Whh   = (const float*)d_in[4];
    const float* bih   = (const float*)d_in[5];
    const float* bhh   = (const float*)d_in[6];
    const float* dW1   = (const float*)d_in[7];
    const float* db1   = (const float*)d_in[8];
    const float* dW2   = (const float*)d_in[9];
    const float* db2   = (const float*)d_in[10];
    float* out = (float*)d_out;

    const int RNN_SMEM = Kseg * WS * 5 * 16;   // 153600 B
    cudaFuncSetAttribute(rnn_kernel,
                         cudaFuncAttributeMaxDynamicSharedMemorySize,
                         RNN_SMEM);

    cudaMemcpyToSymbolAsync(cWih, Wih, G * WS * sizeof(float), 0,
                            cudaMemcpyDeviceToDevice);
    cudaMemcpyToSymbolAsync(cbih, bih, G * sizeof(float), 0,
                            cudaMemcpyDeviceToDevice);
    cudaMemcpyToSymbolAsync(cbhh, bhh, G * sizeof(float), 0,
                            cudaMemcpyDeviceToDevice);

    prep_kernel<<<801, 256>>>(x, enc_W, enc_b, dW1, db1, dW2, db2);
    rnn_kernel<<<128, 128, RNN_SMEM>>>(Whh, bhh, out);
}